// round 6
// baseline (speedup 1.0000x reference)
#include <cuda_runtime.h>
#include <cstdint>
#include <cstdio>

#define TOK   2048
#define NBAT  2
#define NH    16
#define DHD   64
#define DMOD  1024
#define MROWS 4096   /* B*N */
#define FF    4096

// ---------------- scratch (static device globals; no runtime allocation) ---
__device__ float g_x2 [MROWS * DMOD];            // 16 MB : x after attn residual
__device__ float g_xf2[MROWS * DMOD];            // 16 MB : LN3 output
__device__ float g_h  [(size_t)MROWS * 2 * FF];  // 128 MB: FF1 output
__device__ float g_act[(size_t)MROWS * FF];      // 64 MB : geglu output

// ---------------- helpers --------------------------------------------------
__device__ __forceinline__ uint32_t f2tf32(float x) {
    uint32_t t;
    asm("cvt.rna.tf32.f32 %0, %1;" : "=r"(t) : "f"(x));
    return t;
}
__device__ __forceinline__ float f2tf32f(float x) { return __uint_as_float(f2tf32(x)); }

__device__ __forceinline__ void mma_tf32(float c[4], const uint32_t a[4],
                                         uint32_t b0, uint32_t b1) {
    asm volatile(
        "mma.sync.aligned.m16n8k8.row.col.f32.tf32.tf32.f32 "
        "{%0,%1,%2,%3}, {%4,%5,%6,%7}, {%8,%9}, {%0,%1,%2,%3};\n"
        : "+f"(c[0]), "+f"(c[1]), "+f"(c[2]), "+f"(c[3])
        : "r"(a[0]), "r"(a[1]), "r"(a[2]), "r"(a[3]), "r"(b0), "r"(b1));
}

__device__ __forceinline__ float gelu_exact(float x) {
    return 0.5f * x * (1.0f + erff(x * 0.70710678118654752f));
}

// ---------------- LayerNorm (one block per row of 1024) --------------------
__global__ __launch_bounds__(256)
void ln_kernel(const float* __restrict__ x, const float* __restrict__ gw,
               const float* __restrict__ bw, float* __restrict__ y) {
    __shared__ float red[16];
    const int row = blockIdx.x;
    const int tid = threadIdx.x;
    const float4 v = reinterpret_cast<const float4*>(x + (size_t)row * DMOD)[tid];
    float s  = v.x + v.y + v.z + v.w;
    float ss = v.x * v.x + v.y * v.y + v.z * v.z + v.w * v.w;
#pragma unroll
    for (int o = 16; o > 0; o >>= 1) {
        s  += __shfl_xor_sync(0xffffffffu, s,  o);
        ss += __shfl_xor_sync(0xffffffffu, ss, o);
    }
    if ((tid & 31) == 0) { red[tid >> 5] = s; red[8 + (tid >> 5)] = ss; }
    __syncthreads();
    float ts = 0.f, tss = 0.f;
#pragma unroll
    for (int w = 0; w < 8; w++) { ts += red[w]; tss += red[8 + w]; }
    const float mu  = ts * (1.0f / DMOD);
    const float var = tss * (1.0f / DMOD) - mu * mu;
    const float rs  = rsqrtf(var + 1e-5f);
    const float4 gv = reinterpret_cast<const float4*>(gw)[tid];
    const float4 bv = reinterpret_cast<const float4*>(bw)[tid];
    float4 o;
    o.x = (v.x - mu) * rs * gv.x + bv.x;
    o.y = (v.y - mu) * rs * gv.y + bv.y;
    o.z = (v.z - mu) * rs * gv.z + bv.z;
    o.w = (v.w - mu) * rs * gv.w + bv.w;
    reinterpret_cast<float4*>(y + (size_t)row * DMOD)[tid] = o;
}

// ---------------- generic TF32 GEMM ----------------------------------------
// C[M,N] = A[M,K] @ B[K,N] (+bias[N]) (+res[M,N])
// AMODE 0: A row-major.  AMODE 1: A is inter_out (B,H,TOK,DHD), logical col = h*64+dh.
// OMODE 0: C row-major ldc=N.  OMODE 1: scatter to (B*H, TOK, DHD) layout (q/k/v_bh).
constexpr int BM = 128, BN = 128, BK = 32;

template <int AMODE, int OMODE>
__global__ __launch_bounds__(256)
void gemm_tf32_kernel(const float* __restrict__ A, const float* __restrict__ B,
                      float* __restrict__ C, int M, int N, int K,
                      const float* __restrict__ bias, const float* __restrict__ res) {
    __shared__ float As[BM][BK + 4];
    __shared__ float Bs[BK][BN + 4];

    const int tid  = threadIdx.x;
    const int wid  = tid >> 5;
    const int lane = tid & 31;
    const int g    = lane >> 2;
    const int tg   = lane & 3;
    const int m0   = blockIdx.y * BM;
    const int n0   = blockIdx.x * BN;
    const int wm   = (wid & 3) * 32;   // 4 warps along M, 32 rows each
    const int wn   = (wid >> 2) * 64;  // 2 warps along N, 64 cols each

    float acc[2][8][4];
#pragma unroll
    for (int i = 0; i < 2; i++)
#pragma unroll
        for (int j = 0; j < 8; j++)
#pragma unroll
            for (int k = 0; k < 4; k++) acc[i][j][k] = 0.f;

    float4 aReg[4], bReg[4];

    auto loadG = [&](int kb) {
#pragma unroll
        for (int i = 0; i < 4; i++) {
            int s = tid + i * 256;
            int r = s >> 3, c = (s & 7) << 2;
            int gm = m0 + r, gk = kb + c;
            const float* p;
            if (AMODE == 0) {
                p = A + (size_t)gm * K + gk;
            } else {
                int bb = gm >> 11, nn = gm & (TOK - 1);
                int hh = gk >> 6, dd = gk & (DHD - 1);
                p = A + (((size_t)(bb * NH + hh) * TOK + nn) * DHD + dd);
            }
            aReg[i] = *reinterpret_cast<const float4*>(p);
        }
#pragma unroll
        for (int i = 0; i < 4; i++) {
            int s = tid + i * 256;
            int r = s >> 5, c = (s & 31) << 2;
            bReg[i] = *reinterpret_cast<const float4*>(B + (size_t)(kb + r) * N + n0 + c);
        }
    };
    auto stShared = [&]() {
#pragma unroll
        for (int i = 0; i < 4; i++) {
            int s = tid + i * 256;
            int r = s >> 3, c = (s & 7) << 2;
            float4 v = aReg[i];
            float4 w = make_float4(f2tf32f(v.x), f2tf32f(v.y), f2tf32f(v.z), f2tf32f(v.w));
            *reinterpret_cast<float4*>(&As[r][c]) = w;
        }
#pragma unroll
        for (int i = 0; i < 4; i++) {
            int s = tid + i * 256;
            int r = s >> 5, c = (s & 31) << 2;
            float4 v = bReg[i];
            float4 w = make_float4(f2tf32f(v.x), f2tf32f(v.y), f2tf32f(v.z), f2tf32f(v.w));
            *reinterpret_cast<float4*>(&Bs[r][c]) = w;
        }
    };

    const int ktiles = K / BK;
    loadG(0);
    for (int kb = 0; kb < ktiles; kb++) {
        __syncthreads();
        stShared();
        __syncthreads();
        if (kb + 1 < ktiles) loadG((kb + 1) * BK);  // overlap next loads with mma
#pragma unroll
        for (int kk = 0; kk < BK; kk += 8) {
            uint32_t af[2][4];
#pragma unroll
            for (int mt = 0; mt < 2; mt++) {
                int r = wm + mt * 16;
                af[mt][0] = __float_as_uint(As[r + g][kk + tg]);
                af[mt][1] = __float_as_uint(As[r + 8 + g][kk + tg]);
                af[mt][2] = __float_as_uint(As[r + g][kk + tg + 4]);
                af[mt][3] = __float_as_uint(As[r + 8 + g][kk + tg + 4]);
            }
            uint32_t bf[8][2];
#pragma unroll
            for (int nt = 0; nt < 8; nt++) {
                bf[nt][0] = __float_as_uint(Bs[kk + tg][wn + nt * 8 + g]);
                bf[nt][1] = __float_as_uint(Bs[kk + tg + 4][wn + nt * 8 + g]);
            }
#pragma unroll
            for (int mt = 0; mt < 2; mt++)
#pragma unroll
                for (int nt = 0; nt < 8; nt++)
                    mma_tf32(acc[mt][nt], af[mt], bf[nt][0], bf[nt][1]);
        }
    }

    // epilogue
#pragma unroll
    for (int mt = 0; mt < 2; mt++) {
        const int r0 = m0 + wm + mt * 16 + g;
        const int r1 = r0 + 8;
#pragma unroll
        for (int nt = 0; nt < 8; nt++) {
            const int c = n0 + wn + nt * 8 + 2 * tg;
            float2 v0 = make_float2(acc[mt][nt][0], acc[mt][nt][1]);
            float2 v1 = make_float2(acc[mt][nt][2], acc[mt][nt][3]);
            if (bias) {
                float2 bb = *reinterpret_cast<const float2*>(bias + c);
                v0.x += bb.x; v0.y += bb.y; v1.x += bb.x; v1.y += bb.y;
            }
            if (OMODE == 0) {
                if (res) {
                    float2 q0r = *reinterpret_cast<const float2*>(res + (size_t)r0 * N + c);
                    float2 q1r = *reinterpret_cast<const float2*>(res + (size_t)r1 * N + c);
                    v0.x += q0r.x; v0.y += q0r.y; v1.x += q1r.x; v1.y += q1r.y;
                }
                *reinterpret_cast<float2*>(C + (size_t)r0 * N + c) = v0;
                *reinterpret_cast<float2*>(C + (size_t)r1 * N + c) = v1;
            } else {
                const int hh = c >> 6, dd = c & (DHD - 1);
                const int b0_ = r0 >> 11, n0_ = r0 & (TOK - 1);
                const int b1_ = r1 >> 11, n1_ = r1 & (TOK - 1);
                *reinterpret_cast<float2*>(
                    C + ((size_t)(b0_ * NH + hh) * TOK + n0_) * DHD + dd) = v0;
                *reinterpret_cast<float2*>(
                    C + ((size_t)(b1_ * NH + hh) * TOK + n1_) * DHD + dd) = v1;
            }
        }
    }
}

// ---------------- flash attention (per (b,h); BM=128, DH=64) ---------------
// Q pre-scaled by 1/8 (exact). Online softmax; P reg->A-frag via quad shuffles.
__global__ __launch_bounds__(256)
void flash_attn_kernel(const float* __restrict__ Q, const float* __restrict__ Kg,
                       const float* __restrict__ V, float* __restrict__ O) {
    extern __shared__ float sm[];
    float(*Ks)[DHD + 4] = reinterpret_cast<float(*)[DHD + 4]>(sm);
    float(*Vs)[DHD + 4] = reinterpret_cast<float(*)[DHD + 4]>(sm + 128 * (DHD + 4));

    const int tid = threadIdx.x, wid = tid >> 5, lane = tid & 31;
    const int g = lane >> 2, tg = lane & 3;
    const int bh = blockIdx.y;
    const int q0 = blockIdx.x * 128;
    const float* Qp = Q + (size_t)bh * TOK * DHD;
    const float* Kp = Kg + (size_t)bh * TOK * DHD;
    const float* Vp = V + (size_t)bh * TOK * DHD;
    float* Op = O + (size_t)bh * TOK * DHD;
    const int wm = wid * 16;             // 8 warps x 16 rows = 128
    const int r0 = q0 + wm + g, r1 = r0 + 8;

    uint32_t qf[8][4];
#pragma unroll
    for (int ks = 0; ks < 8; ks++) {
        int c = ks * 8 + tg;
        qf[ks][0] = f2tf32(Qp[(size_t)r0 * DHD + c] * 0.125f);
        qf[ks][1] = f2tf32(Qp[(size_t)r1 * DHD + c] * 0.125f);
        qf[ks][2] = f2tf32(Qp[(size_t)r0 * DHD + c + 4] * 0.125f);
        qf[ks][3] = f2tf32(Qp[(size_t)r1 * DHD + c + 4] * 0.125f);
    }

    float m0 = -1e30f, m1 = -1e30f, l0 = 0.f, l1 = 0.f;
    float o[8][4];
#pragma unroll
    for (int i = 0; i < 8; i++)
#pragma unroll
        for (int j = 0; j < 4; j++) o[i][j] = 0.f;

    for (int j = 0; j < TOK; j += 128) {
        __syncthreads();
#pragma unroll
        for (int i = 0; i < 8; i++) {
            int s = tid + i * 256;
            int r = s >> 4, c = (s & 15) << 2;
            float4 kv = *reinterpret_cast<const float4*>(Kp + (size_t)(j + r) * DHD + c);
            float4 vv = *reinterpret_cast<const float4*>(Vp + (size_t)(j + r) * DHD + c);
            float4 kc = make_float4(f2tf32f(kv.x), f2tf32f(kv.y), f2tf32f(kv.z), f2tf32f(kv.w));
            float4 vc = make_float4(f2tf32f(vv.x), f2tf32f(vv.y), f2tf32f(vv.z), f2tf32f(vv.w));
            *reinterpret_cast<float4*>(&Ks[r][c]) = kc;
            *reinterpret_cast<float4*>(&Vs[r][c]) = vc;
        }
        __syncthreads();

        // S = (Q/8) K^T  -> 16 rows x 128 cols per warp
        float sc[16][4];
#pragma unroll
        for (int nt = 0; nt < 16; nt++)
#pragma unroll
            for (int k4 = 0; k4 < 4; k4++) sc[nt][k4] = 0.f;
#pragma unroll
        for (int ks = 0; ks < 8; ks++) {
#pragma unroll
            for (int nt = 0; nt < 16; nt++) {
                uint32_t b0 = __float_as_uint(Ks[nt * 8 + g][ks * 8 + tg]);
                uint32_t b1 = __float_as_uint(Ks[nt * 8 + g][ks * 8 + tg + 4]);
                mma_tf32(sc[nt], qf[ks], b0, b1);
            }
        }

        // online softmax (row r0: elems 0,1 ; row r1: elems 2,3)
        float tm0 = -1e30f, tm1 = -1e30f;
#pragma unroll
        for (int nt = 0; nt < 16; nt++) {
            tm0 = fmaxf(tm0, fmaxf(sc[nt][0], sc[nt][1]));
            tm1 = fmaxf(tm1, fmaxf(sc[nt][2], sc[nt][3]));
        }
        tm0 = fmaxf(tm0, __shfl_xor_sync(0xffffffffu, tm0, 1));
        tm0 = fmaxf(tm0, __shfl_xor_sync(0xffffffffu, tm0, 2));
        tm1 = fmaxf(tm1, __shfl_xor_sync(0xffffffffu, tm1, 1));
        tm1 = fmaxf(tm1, __shfl_xor_sync(0xffffffffu, tm1, 2));
        const float nm0 = fmaxf(m0, tm0), nm1 = fmaxf(m1, tm1);
        const float a0 = __expf(m0 - nm0), a1 = __expf(m1 - nm1);
        float ts0 = 0.f, ts1 = 0.f;
#pragma unroll
        for (int nt = 0; nt < 16; nt++) {
            float p0 = __expf(sc[nt][0] - nm0);
            float p1 = __expf(sc[nt][1] - nm0);
            float p2 = __expf(sc[nt][2] - nm1);
            float p3 = __expf(sc[nt][3] - nm1);
            ts0 += p0 + p1; ts1 += p2 + p3;
            sc[nt][0] = f2tf32f(p0); sc[nt][1] = f2tf32f(p1);
            sc[nt][2] = f2tf32f(p2); sc[nt][3] = f2tf32f(p3);
        }
        ts0 += __shfl_xor_sync(0xffffffffu, ts0, 1);
        ts0 += __shfl_xor_sync(0xffffffffu, ts0, 2);
        ts1 += __shfl_xor_sync(0xffffffffu, ts1, 1);
        ts1 += __shfl_xor_sync(0xffffffffu, ts1, 2);
        l0 = l0 * a0 + ts0; l1 = l1 * a1 + ts1;
        m0 = nm0; m1 = nm1;
#pragma unroll
        for (int nt = 0; nt < 8; nt++) {
            o[nt][0] *= a0; o[nt][1] *= a0; o[nt][2] *= a1; o[nt][3] *= a1;
        }

        // O += P @ V  (C-frag -> A-frag remap via quad shuffles)
        const int qb = lane & ~3;
        const int srcA = qb + (tg >> 1);
        const int srcB = srcA + 2;
        const bool odd = (tg & 1);
#pragma unroll
        for (int kt = 0; kt < 16; kt++) {
            float p0 = sc[kt][0], p1 = sc[kt][1], p2 = sc[kt][2], p3 = sc[kt][3];
            float e0 = __shfl_sync(0xffffffffu, p0, srcA);
            float e1 = __shfl_sync(0xffffffffu, p1, srcA);
            float e2 = __shfl_sync(0xffffffffu, p2, srcA);
            float e3 = __shfl_sync(0xffffffffu, p3, srcA);
            float h0 = __shfl_sync(0xffffffffu, p0, srcB);
            float h1 = __shfl_sync(0xffffffffu, p1, srcB);
            float h2 = __shfl_sync(0xffffffffu, p2, srcB);
            float h3 = __shfl_sync(0xffffffffu, p3, srcB);
            uint32_t af[4];
            af[0] = __float_as_uint(odd ? e1 : e0);
            af[1] = __float_as_uint(odd ? e3 : e2);
            af[2] = __float_as_uint(odd ? h1 : h0);
            af[3] = __float_as_uint(odd ? h3 : h2);
#pragma unroll
            for (int nt = 0; nt < 8; nt++) {
                uint32_t b0 = __float_as_uint(Vs[kt * 8 + tg][nt * 8 + g]);
                uint32_t b1 = __float_as_uint(Vs[kt * 8 + tg + 4][nt * 8 + g]);
                mma_tf32(o[nt], af, b0, b1);
            }
        }
    }

    const float il0 = 1.f / l0, il1 = 1.f / l1;
#pragma unroll
    for (int nt = 0; nt < 8; nt++) {
        int c = nt * 8 + 2 * tg;
        float2 v0 = make_float2(o[nt][0] * il0, o[nt][1] * il0);
        float2 v1 = make_float2(o[nt][2] * il1, o[nt][3] * il1);
        *reinterpret_cast<float2*>(Op + (size_t)r0 * DHD + c) = v0;
        *reinterpret_cast<float2*>(Op + (size_t)r1 * DHD + c) = v1;
    }
}

// ---------------- GEGLU ----------------------------------------------------
__global__ __launch_bounds__(256)
void geglu_kernel(const float* __restrict__ h, float* __restrict__ act) {
    const int idx = blockIdx.x * 256 + threadIdx.x;  // float4 index over MROWS*FF/4
    const int m = idx >> 10;                         // FF/4 = 1024 float4 per row
    const int c = (idx & 1023) << 2;
    const float4 a  = *reinterpret_cast<const float4*>(h + (size_t)m * (2 * FF) + c);
    const float4 gt = *reinterpret_cast<const float4*>(h + (size_t)m * (2 * FF) + FF + c);
    float4 o;
    o.x = a.x * gelu_exact(gt.x);
    o.y = a.y * gelu_exact(gt.y);
    o.z = a.z * gelu_exact(gt.z);
    o.w = a.w * gelu_exact(gt.w);
    *reinterpret_cast<float4*>(act + (size_t)m * FF + c) = o;
}

// ---------------- launch ---------------------------------------------------
extern "C" void kernel_launch(void* const* d_in, const int* in_sizes, int n_in,
                              void* d_out, int out_size) {
    (void)in_sizes; (void)n_in; (void)out_size;
    const float* x     = (const float*)d_in[0];
    const float* Wq    = (const float*)d_in[1];
    const float* Wk    = (const float*)d_in[2];
    const float* Wv    = (const float*)d_in[3];
    const float* Wo    = (const float*)d_in[4];
    const float* bo    = (const float*)d_in[5];
    const float* ln1_g = (const float*)d_in[6];
    const float* ln1_b = (const float*)d_in[7];
    const float* ln3_g = (const float*)d_in[8];
    const float* ln3_b = (const float*)d_in[9];
    const float* Wff1  = (const float*)d_in[10];
    const float* bff1  = (const float*)d_in[11];
    const float* Wff2  = (const float*)d_in[12];
    const float* bff2  = (const float*)d_in[13];

    float* out = (float*)d_out;
    const size_t SZ = (size_t)MROWS * DMOD;  // 4194304
    float* out_x  = out;            // x
    float* out_q  = out + SZ;       // q_bh
    float* out_k  = out + 2 * SZ;   // k_bh
    float* out_v  = out + 3 * SZ;   // v_bh
    float* out_io = out + 4 * SZ;   // inter_out
    float* out_xf = out + 5 * SZ;   // x_features

    float *x2, *xf2, *hbuf, *actbuf;
    cudaGetSymbolAddress((void**)&x2,     g_x2);
    cudaGetSymbolAddress((void**)&xf2,    g_xf2);
    cudaGetSymbolAddress((void**)&hbuf,   g_h);
    cudaGetSymbolAddress((void**)&actbuf, g_act);

    const dim3 blk(256);
    const dim3 gD(DMOD / BN, MROWS / BM);       // (8, 32)
    const dim3 gF(2 * FF / BN, MROWS / BM);     // (64, 32)

    // 1) LN1 -> x_features
    ln_kernel<<<MROWS, 256>>>(x, ln1_g, ln1_b, out_xf);

    // 2) QKV GEMMs, scattered directly to (B*H, N, DH)
    gemm_tf32_kernel<0, 1><<<gD, blk>>>(out_xf, Wq, out_q, MROWS, DMOD, DMOD, nullptr, nullptr);
    gemm_tf32_kernel<0, 1><<<gD, blk>>>(out_xf, Wk, out_k, MROWS, DMOD, DMOD, nullptr, nullptr);
    gemm_tf32_kernel<0, 1><<<gD, blk>>>(out_xf, Wv, out_v, MROWS, DMOD, DMOD, nullptr, nullptr);

    // 3) attention -> inter_out (B,H,N,DH)
    const int smem = 2 * 128 * (DHD + 4) * (int)sizeof(float);  // 69632 B
    cudaFuncSetAttribute(flash_attn_kernel, cudaFuncAttributeMaxDynamicSharedMemorySize, smem);
    flash_attn_kernel<<<dim3(TOK / 128, NBAT * NH), 256, smem>>>(out_q, out_k, out_v, out_io);

    // 4) Wo GEMM (gather-A from inter_out layout) + bo + residual x -> x2
    gemm_tf32_kernel<1, 0><<<gD, blk>>>(out_io, Wo, x2, MROWS, DMOD, DMOD, bo, x);

    // 5) LN3 -> xf2
    ln_kernel<<<MROWS, 256>>>(x2, ln3_g, ln3_b, xf2);

    // 6) FF1 GEMM (+bff1) -> h
    gemm_tf32_kernel<0, 0><<<gF, blk>>>(xf2, Wff1, hbuf, MROWS, 2 * FF, DMOD, bff1, nullptr);

    // 7) GEGLU -> act
    geglu_kernel<<<(MROWS * (FF / 4)) / 256, 256>>>(hbuf, actbuf);

    // 8) FF2 GEMM (+bff2) + residual x2 -> final x
    gemm_tf32_kernel<0, 0><<<gD, blk>>>(actbuf, Wff2, out_x, MROWS, DMOD, FF, bff2, x2);
}

// round 7
// speedup vs baseline: 1.2913x; 1.2913x over previous
#include <cuda_runtime.h>
#include <cstdint>
#include <cstdio>

#define TOK   2048
#define NBAT  2
#define NH    16
#define DHD   64
#define DMOD  1024
#define MROWS 4096   /* B*N */
#define FF    4096

// ---------------- scratch (static device globals; no runtime allocation) ---
__device__ float g_x2 [MROWS * DMOD];            // 16 MB : x after attn residual
__device__ float g_xf2[MROWS * DMOD];            // 16 MB : LN3 output
__device__ float g_h  [(size_t)MROWS * 2 * FF];  // 128 MB: FF1 output
__device__ float g_act[(size_t)MROWS * FF];      // 64 MB : geglu output

// ---------------- helpers --------------------------------------------------
__device__ __forceinline__ uint32_t f2tf32(float x) {
    uint32_t t;
    asm("cvt.rna.tf32.f32 %0, %1;" : "=r"(t) : "f"(x));
    return t;
}
__device__ __forceinline__ float f2tf32f(float x) { return __uint_as_float(f2tf32(x)); }

__device__ __forceinline__ void mma_tf32(float c[4], const uint32_t a[4],
                                         uint32_t b0, uint32_t b1) {
    asm volatile(
        "mma.sync.aligned.m16n8k8.row.col.f32.tf32.tf32.f32 "
        "{%0,%1,%2,%3}, {%4,%5,%6,%7}, {%8,%9}, {%0,%1,%2,%3};\n"
        : "+f"(c[0]), "+f"(c[1]), "+f"(c[2]), "+f"(c[3])
        : "r"(a[0]), "r"(a[1]), "r"(a[2]), "r"(a[3]), "r"(b0), "r"(b1));
}

__device__ __forceinline__ void cp_async16(uint32_t dst, const void* src) {
    asm volatile("cp.async.cg.shared.global [%0], [%1], 16;\n" :: "r"(dst), "l"(src));
}
__device__ __forceinline__ void cp_commit() {
    asm volatile("cp.async.commit_group;\n" ::: "memory");
}
__device__ __forceinline__ void cp_wait1() {
    asm volatile("cp.async.wait_group 1;\n" ::: "memory");
}

__device__ __forceinline__ float gelu_exact(float x) {
    return 0.5f * x * (1.0f + erff(x * 0.70710678118654752f));
}

// ---------------- LayerNorm (one block per row of 1024) --------------------
__global__ __launch_bounds__(256)
void ln_kernel(const float* __restrict__ x, const float* __restrict__ gw,
               const float* __restrict__ bw, float* __restrict__ y) {
    __shared__ float red[16];
    const int row = blockIdx.x;
    const int tid = threadIdx.x;
    const float4 v = reinterpret_cast<const float4*>(x + (size_t)row * DMOD)[tid];
    float s  = v.x + v.y + v.z + v.w;
    float ss = v.x * v.x + v.y * v.y + v.z * v.z + v.w * v.w;
#pragma unroll
    for (int o = 16; o > 0; o >>= 1) {
        s  += __shfl_xor_sync(0xffffffffu, s,  o);
        ss += __shfl_xor_sync(0xffffffffu, ss, o);
    }
    if ((tid & 31) == 0) { red[tid >> 5] = s; red[8 + (tid >> 5)] = ss; }
    __syncthreads();
    float ts = 0.f, tss = 0.f;
#pragma unroll
    for (int w = 0; w < 8; w++) { ts += red[w]; tss += red[8 + w]; }
    const float mu  = ts * (1.0f / DMOD);
    const float var = tss * (1.0f / DMOD) - mu * mu;
    const float rs  = rsqrtf(var + 1e-5f);
    const float4 gv = reinterpret_cast<const float4*>(gw)[tid];
    const float4 bv = reinterpret_cast<const float4*>(bw)[tid];
    float4 o;
    o.x = (v.x - mu) * rs * gv.x + bv.x;
    o.y = (v.y - mu) * rs * gv.y + bv.y;
    o.z = (v.z - mu) * rs * gv.z + bv.z;
    o.w = (v.w - mu) * rs * gv.w + bv.w;
    reinterpret_cast<float4*>(y + (size_t)row * DMOD)[tid] = o;
}

// ---------------- TF32 GEMM v2: CTA 128x256, warp 64x64, cp.async 3-stage ---
// smem layout per stage: As[128][36] then Bs[32][264] (floats).
// A stride 36 -> frag banks (g*4+tg) all distinct; B stride 264 -> (tg*8+g) all distinct.
constexpr int BM = 128, BN = 256, BK = 32, STAGES = 3;
constexpr int LDA_S = 36, LDB_S = 264;
constexpr int STAGE_F = BM * LDA_S + BK * LDB_S;               // 13056 floats
constexpr int SMEM_GEMM = STAGES * STAGE_F * 4;                // 156672 bytes

// AMODE 0: A row-major [M][K].  AMODE 1: A gathered from inter_out (B,H,TOK,DHD).
template <int AMODE>
struct ALoader {
    static __device__ __forceinline__ const float* ptr(const float* A, int gm, int gk, int K) {
        if (AMODE == 0) return A + (size_t)gm * K + gk;
        int bb = gm >> 11, nn = gm & (TOK - 1);
        int hh = gk >> 6,  dd = gk & (DHD - 1);
        return A + (((size_t)(bb * NH + hh) * TOK + nn) * DHD + dd);
    }
};

template <int AMODE>
__device__ __forceinline__ void gemm_load_stage(
    const float* __restrict__ A, const float* __restrict__ B, int ldb,
    int m0, int nb, int kb, int K, uint32_t smem_stage) {
#pragma unroll
    for (int i = 0; i < 4; i++) {                // A: 128x32 = 1024 chunks / 256 thr
        int c = i * 256 + threadIdx.x;
        int row = c >> 3, kc = (c & 7) << 2;
        const float* src = ALoader<AMODE>::ptr(A, m0 + row, kb + kc, K);
        cp_async16(smem_stage + (uint32_t)(row * LDA_S + kc) * 4u, src);
    }
    const uint32_t bs = smem_stage + (uint32_t)(BM * LDA_S) * 4u;
#pragma unroll
    for (int i = 0; i < 8; i++) {                // B: 32x256 = 2048 chunks / 256 thr
        int c = i * 256 + threadIdx.x;
        int row = c >> 6, col = (c & 63) << 2;
        cp_async16(bs + (uint32_t)(row * LDB_S + col) * 4u,
                   B + (size_t)(kb + row) * ldb + nb + col);
    }
}

__device__ __forceinline__ void gemm_compute_stage(
    const float* __restrict__ st, int wm, int wn, float acc[4][8][4]) {
    const int lane = threadIdx.x & 31;
    const int g = lane >> 2, tg = lane & 3;
    const float* As = st;
    const float* Bs = st + BM * LDA_S;
#pragma unroll
    for (int kk = 0; kk < BK; kk += 8) {
        uint32_t af[4][4];
#pragma unroll
        for (int mt = 0; mt < 4; mt++) {
            const float* ar = As + (wm + mt * 16 + g) * LDA_S + kk + tg;
            af[mt][0] = f2tf32(ar[0]);
            af[mt][1] = f2tf32(ar[8 * LDA_S]);
            af[mt][2] = f2tf32(ar[4]);
            af[mt][3] = f2tf32(ar[8 * LDA_S + 4]);
        }
        uint32_t bf[8][2];
#pragma unroll
        for (int nt = 0; nt < 8; nt++) {
            const float* br = Bs + (kk + tg) * LDB_S + wn + nt * 8 + g;
            bf[nt][0] = f2tf32(br[0]);
            bf[nt][1] = f2tf32(br[4 * LDB_S]);
        }
#pragma unroll
        for (int mt = 0; mt < 4; mt++)
#pragma unroll
            for (int nt = 0; nt < 8; nt++)
                mma_tf32(acc[mt][nt], af[mt], bf[nt][0], bf[nt][1]);
    }
}

// ---- standard output: C row-major (ldc = N), optional bias + residual -----
template <int AMODE>
__global__ __launch_bounds__(256)
void gemm3_kernel(const float* __restrict__ A, const float* __restrict__ B,
                  float* __restrict__ C, int M, int N, int K,
                  const float* __restrict__ bias, const float* __restrict__ res) {
    extern __shared__ float sm[];
    const uint32_t smem_u = (uint32_t)__cvta_generic_to_shared(sm);
    const int tid = threadIdx.x, wid = tid >> 5, lane = tid & 31;
    const int g = lane >> 2, tg = lane & 3;
    const int m0 = blockIdx.y * BM;
    const int n0 = blockIdx.x * BN;
    const int wm = (wid & 1) * 64;
    const int wn = (wid >> 1) * 64;

    float acc[4][8][4];
#pragma unroll
    for (int i = 0; i < 4; i++)
#pragma unroll
        for (int j = 0; j < 8; j++)
#pragma unroll
            for (int k = 0; k < 4; k++) acc[i][j][k] = 0.f;

    const int T = K / BK;
    gemm_load_stage<AMODE>(A, B, N, m0, n0, 0, K, smem_u);
    cp_commit();
    gemm_load_stage<AMODE>(A, B, N, m0, n0, BK, K, smem_u + STAGE_F * 4);
    cp_commit();

    int s = 0;
    for (int kt = 0; kt < T; kt++) {
        cp_wait1();
        __syncthreads();
        if (kt + 2 < T) {
            int s2 = (s + 2 >= STAGES) ? s + 2 - STAGES : s + 2;
            gemm_load_stage<AMODE>(A, B, N, m0, n0, (kt + 2) * BK, K,
                                   smem_u + (uint32_t)s2 * STAGE_F * 4);
        }
        cp_commit();
        gemm_compute_stage(sm + s * STAGE_F, wm, wn, acc);
        s = (s + 1 == STAGES) ? 0 : s + 1;
    }

#pragma unroll
    for (int mt = 0; mt < 4; mt++) {
        const int r0 = m0 + wm + mt * 16 + g;
        const int r1 = r0 + 8;
#pragma unroll
        for (int nt = 0; nt < 8; nt++) {
            const int c = n0 + wn + nt * 8 + 2 * tg;
            float2 v0 = make_float2(acc[mt][nt][0], acc[mt][nt][1]);
            float2 v1 = make_float2(acc[mt][nt][2], acc[mt][nt][3]);
            if (bias) {
                float2 bb = *reinterpret_cast<const float2*>(bias + c);
                v0.x += bb.x; v0.y += bb.y; v1.x += bb.x; v1.y += bb.y;
            }
            if (res) {
                float2 q0r = *reinterpret_cast<const float2*>(res + (size_t)r0 * N + c);
                float2 q1r = *reinterpret_cast<const float2*>(res + (size_t)r1 * N + c);
                v0.x += q0r.x; v0.y += q0r.y; v1.x += q1r.x; v1.y += q1r.y;
            }
            *reinterpret_cast<float2*>(C + (size_t)r0 * N + c) = v0;
            *reinterpret_cast<float2*>(C + (size_t)r1 * N + c) = v1;
        }
    }
}

// ---- fused QKV: one GEMM over N=3072, scatter into q_bh/k_bh/v_bh ---------
__global__ __launch_bounds__(256)
void gemm_qkv_kernel(const float* __restrict__ A,
                     const float* __restrict__ Wq, const float* __restrict__ Wk,
                     const float* __restrict__ Wv,
                     float* __restrict__ Cq, float* __restrict__ Ck,
                     float* __restrict__ Cv) {
    extern __shared__ float sm[];
    const uint32_t smem_u = (uint32_t)__cvta_generic_to_shared(sm);
    const int tid = threadIdx.x, wid = tid >> 5, lane = tid & 31;
    const int g = lane >> 2, tg = lane & 3;
    const int m0 = blockIdx.y * BM;
    const int arr = blockIdx.x >> 2;                 // 0..2 : which weight/output
    const int nb  = (blockIdx.x & 3) * BN;           // column base within the array
    const float* B = (arr == 0) ? Wq : (arr == 1) ? Wk : Wv;
    float* C = (arr == 0) ? Cq : (arr == 1) ? Ck : Cv;
    const int wm = (wid & 1) * 64;
    const int wn = (wid >> 1) * 64;
    const int K = DMOD;

    float acc[4][8][4];
#pragma unroll
    for (int i = 0; i < 4; i++)
#pragma unroll
        for (int j = 0; j < 8; j++)
#pragma unroll
            for (int k = 0; k < 4; k++) acc[i][j][k] = 0.f;

    const int T = K / BK;
    gemm_load_stage<0>(A, B, DMOD, m0, nb, 0, K, smem_u);
    cp_commit();
    gemm_load_stage<0>(A, B, DMOD, m0, nb, BK, K, smem_u + STAGE_F * 4);
    cp_commit();

    int s = 0;
    for (int kt = 0; kt < T; kt++) {
        cp_wait1();
        __syncthreads();
        if (kt + 2 < T) {
            int s2 = (s + 2 >= STAGES) ? s + 2 - STAGES : s + 2;
            gemm_load_stage<0>(A, B, DMOD, m0, nb, (kt + 2) * BK, K,
                               smem_u + (uint32_t)s2 * STAGE_F * 4);
        }
        cp_commit();
        gemm_compute_stage(sm + s * STAGE_F, wm, wn, acc);
        s = (s + 1 == STAGES) ? 0 : s + 1;
    }

    // scatter to (B*H, TOK, DHD)
#pragma unroll
    for (int mt = 0; mt < 4; mt++) {
        const int r0 = m0 + wm + mt * 16 + g;
        const int r1 = r0 + 8;
        const int b0_ = r0 >> 11, n0_ = r0 & (TOK - 1);
        const int b1_ = r1 >> 11, n1_ = r1 & (TOK - 1);
#pragma unroll
        for (int nt = 0; nt < 8; nt++) {
            const int cl = nb + wn + nt * 8 + 2 * tg;
            const int hh = cl >> 6, dd = cl & (DHD - 1);
            float2 v0 = make_float2(acc[mt][nt][0], acc[mt][nt][1]);
            float2 v1 = make_float2(acc[mt][nt][2], acc[mt][nt][3]);
            *reinterpret_cast<float2*>(
                C + ((size_t)(b0_ * NH + hh) * TOK + n0_) * DHD + dd) = v0;
            *reinterpret_cast<float2*>(
                C + ((size_t)(b1_ * NH + hh) * TOK + n1_) * DHD + dd) = v1;
        }
    }
}

// ---------------- flash attention (per (b,h); BM=128, DH=64) ---------------
__global__ __launch_bounds__(256)
void flash_attn_kernel(const float* __restrict__ Q, const float* __restrict__ Kg,
                       const float* __restrict__ V, float* __restrict__ O) {
    extern __shared__ float sm[];
    float(*Ks)[DHD + 4] = reinterpret_cast<float(*)[DHD + 4]>(sm);
    float(*Vs)[DHD + 4] = reinterpret_cast<float(*)[DHD + 4]>(sm + 128 * (DHD + 4));

    const int tid = threadIdx.x, wid = tid >> 5, lane = tid & 31;
    const int g = lane >> 2, tg = lane & 3;
    const int bh = blockIdx.y;
    const int q0 = blockIdx.x * 128;
    const float* Qp = Q + (size_t)bh * TOK * DHD;
    const float* Kp = Kg + (size_t)bh * TOK * DHD;
    const float* Vp = V + (size_t)bh * TOK * DHD;
    float* Op = O + (size_t)bh * TOK * DHD;
    const int wm = wid * 16;
    const int r0 = q0 + wm + g, r1 = r0 + 8;

    uint32_t qf[8][4];
#pragma unroll
    for (int ks = 0; ks < 8; ks++) {
        int c = ks * 8 + tg;
        qf[ks][0] = f2tf32(Qp[(size_t)r0 * DHD + c] * 0.125f);
        qf[ks][1] = f2tf32(Qp[(size_t)r1 * DHD + c] * 0.125f);
        qf[ks][2] = f2tf32(Qp[(size_t)r0 * DHD + c + 4] * 0.125f);
        qf[ks][3] = f2tf32(Qp[(size_t)r1 * DHD + c + 4] * 0.125f);
    }

    float m0 = -1e30f, m1 = -1e30f, l0 = 0.f, l1 = 0.f;
    float o[8][4];
#pragma unroll
    for (int i = 0; i < 8; i++)
#pragma unroll
        for (int j = 0; j < 4; j++) o[i][j] = 0.f;

    for (int j = 0; j < TOK; j += 128) {
        __syncthreads();
#pragma unroll
        for (int i = 0; i < 8; i++) {
            int s = tid + i * 256;
            int r = s >> 4, c = (s & 15) << 2;
            float4 kv = *reinterpret_cast<const float4*>(Kp + (size_t)(j + r) * DHD + c);
            float4 vv = *reinterpret_cast<const float4*>(Vp + (size_t)(j + r) * DHD + c);
            float4 kc = make_float4(f2tf32f(kv.x), f2tf32f(kv.y), f2tf32f(kv.z), f2tf32f(kv.w));
            float4 vc = make_float4(f2tf32f(vv.x), f2tf32f(vv.y), f2tf32f(vv.z), f2tf32f(vv.w));
            *reinterpret_cast<float4*>(&Ks[r][c]) = kc;
            *reinterpret_cast<float4*>(&Vs[r][c]) = vc;
        }
        __syncthreads();

        float sc[16][4];
#pragma unroll
        for (int nt = 0; nt < 16; nt++)
#pragma unroll
            for (int k4 = 0; k4 < 4; k4++) sc[nt][k4] = 0.f;
#pragma unroll
        for (int ks = 0; ks < 8; ks++) {
#pragma unroll
            for (int nt = 0; nt < 16; nt++) {
                uint32_t b0 = __float_as_uint(Ks[nt * 8 + g][ks * 8 + tg]);
                uint32_t b1 = __float_as_uint(Ks[nt * 8 + g][ks * 8 + tg + 4]);
                mma_tf32(sc[nt], qf[ks], b0, b1);
            }
        }

        float tm0 = -1e30f, tm1 = -1e30f;
#pragma unroll
        for (int nt = 0; nt < 16; nt++) {
            tm0 = fmaxf(tm0, fmaxf(sc[nt][0], sc[nt][1]));
            tm1 = fmaxf(tm1, fmaxf(sc[nt][2], sc[nt][3]));
        }
        tm0 = fmaxf(tm0, __shfl_xor_sync(0xffffffffu, tm0, 1));
        tm0 = fmaxf(tm0, __shfl_xor_sync(0xffffffffu, tm0, 2));
        tm1 = fmaxf(tm1, __shfl_xor_sync(0xffffffffu, tm1, 1));
        tm1 = fmaxf(tm1, __shfl_xor_sync(0xffffffffu, tm1, 2));
        const float nm0 = fmaxf(m0, tm0), nm1 = fmaxf(m1, tm1);
        const float a0 = __expf(m0 - nm0), a1 = __expf(m1 - nm1);
        float ts0 = 0.f, ts1 = 0.f;
#pragma unroll
        for (int nt = 0; nt < 16; nt++) {
            float p0 = __expf(sc[nt][0] - nm0);
            float p1 = __expf(sc[nt][1] - nm0);
            float p2 = __expf(sc[nt][2] - nm1);
            float p3 = __expf(sc[nt][3] - nm1);
            ts0 += p0 + p1; ts1 += p2 + p3;
            sc[nt][0] = f2tf32f(p0); sc[nt][1] = f2tf32f(p1);
            sc[nt][2] = f2tf32f(p2); sc[nt][3] = f2tf32f(p3);
        }
        ts0 += __shfl_xor_sync(0xffffffffu, ts0, 1);
        ts0 += __shfl_xor_sync(0xffffffffu, ts0, 2);
        ts1 += __shfl_xor_sync(0xffffffffu, ts1, 1);
        ts1 += __shfl_xor_sync(0xffffffffu, ts1, 2);
        l0 = l0 * a0 + ts0; l1 = l1 * a1 + ts1;
        m0 = nm0; m1 = nm1;
#pragma unroll
        for (int nt = 0; nt < 8; nt++) {
            o[nt][0] *= a0; o[nt][1] *= a0; o[nt][2] *= a1; o[nt][3] *= a1;
        }

        const int qb = lane & ~3;
        const int srcA = qb + (tg >> 1);
        const int srcB = srcA + 2;
        const bool odd = (tg & 1);
#pragma unroll
        for (int kt = 0; kt < 16; kt++) {
            float p0 = sc[kt][0], p1 = sc[kt][1], p2 = sc[kt][2], p3 = sc[kt][3];
            float e0 = __shfl_sync(0xffffffffu, p0, srcA);
            float e1 = __shfl_sync(0xffffffffu, p1, srcA);
            float e2 = __shfl_sync(0xffffffffu, p2, srcA);
            float e3 = __shfl_sync(0xffffffffu, p3, srcA);
            float h0 = __shfl_sync(0xffffffffu, p0, srcB);
            float h1 = __shfl_sync(0xffffffffu, p1, srcB);
            float h2 = __shfl_sync(0xffffffffu, p2, srcB);
            float h3 = __shfl_sync(0xffffffffu, p3, srcB);
            uint32_t af[4];
            af[0] = __float_as_uint(odd ? e1 : e0);
            af[1] = __float_as_uint(odd ? e3 : e2);
            af[2] = __float_as_uint(odd ? h1 : h0);
            af[3] = __float_as_uint(odd ? h3 : h2);
#pragma unroll
            for (int nt = 0; nt < 8; nt++) {
                uint32_t b0 = __float_as_uint(Vs[kt * 8 + tg][nt * 8 + g]);
                uint32_t b1 = __float_as_uint(Vs[kt * 8 + tg + 4][nt * 8 + g]);
                mma_tf32(o[nt], af, b0, b1);
            }
        }
    }

    const float il0 = 1.f / l0, il1 = 1.f / l1;
#pragma unroll
    for (int nt = 0; nt < 8; nt++) {
        int c = nt * 8 + 2 * tg;
        float2 v0 = make_float2(o[nt][0] * il0, o[nt][1] * il0);
        float2 v1 = make_float2(o[nt][2] * il1, o[nt][3] * il1);
        *reinterpret_cast<float2*>(Op + (size_t)r0 * DHD + c) = v0;
        *reinterpret_cast<float2*>(Op + (size_t)r1 * DHD + c) = v1;
    }
}

// ---------------- GEGLU ----------------------------------------------------
__global__ __launch_bounds__(256)
void geglu_kernel(const float* __restrict__ h, float* __restrict__ act) {
    const int idx = blockIdx.x * 256 + threadIdx.x;
    const int m = idx >> 10;
    const int c = (idx & 1023) << 2;
    const float4 a  = *reinterpret_cast<const float4*>(h + (size_t)m * (2 * FF) + c);
    const float4 gt = *reinterpret_cast<const float4*>(h + (size_t)m * (2 * FF) + FF + c);
    float4 o;
    o.x = a.x * gelu_exact(gt.x);
    o.y = a.y * gelu_exact(gt.y);
    o.z = a.z * gelu_exact(gt.z);
    o.w = a.w * gelu_exact(gt.w);
    *reinterpret_cast<float4*>(act + (size_t)m * FF + c) = o;
}

// ---------------- launch ---------------------------------------------------
extern "C" void kernel_launch(void* const* d_in, const int* in_sizes, int n_in,
                              void* d_out, int out_size) {
    (void)in_sizes; (void)n_in; (void)out_size;
    const float* x     = (const float*)d_in[0];
    const float* Wq    = (const float*)d_in[1];
    const float* Wk    = (const float*)d_in[2];
    const float* Wv    = (const float*)d_in[3];
    const float* Wo    = (const float*)d_in[4];
    const float* bo    = (const float*)d_in[5];
    const float* ln1_g = (const float*)d_in[6];
    const float* ln1_b = (const float*)d_in[7];
    const float* ln3_g = (const float*)d_in[8];
    const float* ln3_b = (const float*)d_in[9];
    const float* Wff1  = (const float*)d_in[10];
    const float* bff1  = (const float*)d_in[11];
    const float* Wff2  = (const float*)d_in[12];
    const float* bff2  = (const float*)d_in[13];

    float* out = (float*)d_out;
    const size_t SZ = (size_t)MROWS * DMOD;
    float* out_x  = out;            // x
    float* out_q  = out + SZ;       // q_bh
    float* out_k  = out + 2 * SZ;   // k_bh
    float* out_v  = out + 3 * SZ;   // v_bh
    float* out_io = out + 4 * SZ;   // inter_out
    float* out_xf = out + 5 * SZ;   // x_features

    float *x2, *xf2, *hbuf, *actbuf;
    cudaGetSymbolAddress((void**)&x2,     g_x2);
    cudaGetSymbolAddress((void**)&xf2,    g_xf2);
    cudaGetSymbolAddress((void**)&hbuf,   g_h);
    cudaGetSymbolAddress((void**)&actbuf, g_act);

    static bool attr_done = false;
    if (!attr_done) {
        cudaFuncSetAttribute(gemm_qkv_kernel,
                             cudaFuncAttributeMaxDynamicSharedMemorySize, SMEM_GEMM);
        cudaFuncSetAttribute(gemm3_kernel<0>,
                             cudaFuncAttributeMaxDynamicSharedMemorySize, SMEM_GEMM);
        cudaFuncSetAttribute(gemm3_kernel<1>,
                             cudaFuncAttributeMaxDynamicSharedMemorySize, SMEM_GEMM);
        cudaFuncSetAttribute(flash_attn_kernel,
                             cudaFuncAttributeMaxDynamicSharedMemorySize,
                             2 * 128 * (DHD + 4) * (int)sizeof(float));
        attr_done = true;
    }

    const dim3 blk(256);

    // 1) LN1 -> x_features
    ln_kernel<<<MROWS, 256>>>(x, ln1_g, ln1_b, out_xf);

    // 2) fused QKV GEMM (N = 3072), scattered directly to (B*H, N, DH)
    gemm_qkv_kernel<<<dim3(3 * DMOD / BN, MROWS / BM), blk, SMEM_GEMM>>>(
        out_xf, Wq, Wk, Wv, out_q, out_k, out_v);

    // 3) attention -> inter_out (B,H,N,DH)
    const int smem_fa = 2 * 128 * (DHD + 4) * (int)sizeof(float);
    flash_attn_kernel<<<dim3(TOK / 128, NBAT * NH), 256, smem_fa>>>(
        out_q, out_k, out_v, out_io);

    // 4) Wo GEMM (gather-A from inter_out layout) + bo + residual x -> x2
    gemm3_kernel<1><<<dim3(DMOD / BN, MROWS / BM), blk, SMEM_GEMM>>>(
        out_io, Wo, x2, MROWS, DMOD, DMOD, bo, x);

    // 5) LN3 -> xf2
    ln_kernel<<<MROWS, 256>>>(x2, ln3_g, ln3_b, xf2);

    // 6) FF1 GEMM (+bff1) -> h
    gemm3_kernel<0><<<dim3(2 * FF / BN, MROWS / BM), blk, SMEM_GEMM>>>(
        xf2, Wff1, hbuf, MROWS, 2 * FF, DMOD, bff1, nullptr);

    // 7) GEGLU -> act
    geglu_kernel<<<(MROWS * (FF / 4)) / 256, 256>>>(hbuf, actbuf);

    // 8) FF2 GEMM (+bff2) + residual x2 -> final x
    gemm3_kernel<0><<<dim3(DMOD / BN, MROWS / BM), blk, SMEM_GEMM>>>(
        actbuf, Wff2, out_x, MROWS, DMOD, FF, bff2, x2);
}